// round 14
// baseline (speedup 1.0000x reference)
#include <cuda_runtime.h>
#include <cuda_bf16.h>
#include <math.h>
#include <cstdint>

#define EPS 1e-5f

// ---------------- scratch (static device globals) ----------------
__device__ float g_xA [256*64*64];
__device__ float g_g2 [256*128*128];
__device__ float g_kk1[9*128*128];
__device__ float g_xB [128*128*128];
__device__ float g_g1 [128*256*256];
__device__ float g_kk2[9*256*256];
__device__ float g_xC [64*256*256];
__device__ float g_G  [9437184];       // pac GEMM output, max 576*16384 floats (36 MB)

// ---------------- double instance-norm residual ----------------
__global__ void dinorm_kernel(const float* __restrict__ in, float* __restrict__ out, int N) {
    const int c = blockIdx.x;
    const float* x = in + (size_t)c * N;
    float* y = out + (size_t)c * N;

    float s = 0.f, s2 = 0.f;
    for (int i = threadIdx.x; i < N; i += blockDim.x) {
        float v = x[i];
        s += v; s2 += v * v;
    }
    #pragma unroll
    for (int o = 16; o > 0; o >>= 1) {
        s  += __shfl_down_sync(0xffffffffu, s,  o);
        s2 += __shfl_down_sync(0xffffffffu, s2, o);
    }
    __shared__ float redA[8], redB[8];
    __shared__ float s_m, s_scale;
    int wid = threadIdx.x >> 5, lid = threadIdx.x & 31;
    if (lid == 0) { redA[wid] = s; redB[wid] = s2; }
    __syncthreads();
    if (threadIdx.x == 0) {
        float S = 0.f, S2 = 0.f;
        int nw = blockDim.x >> 5;
        for (int i = 0; i < nw; i++) { S += redA[i]; S2 += redB[i]; }
        float m = S / N;
        float v = S2 / N - m * m;
        if (v < 0.f) v = 0.f;
        float r  = rsqrtf(v + EPS);
        float r2 = rsqrtf(v * (1.f + r) * (1.f + r) + EPS);
        s_m = m; s_scale = (1.f + r) * (1.f + r2);
    }
    __syncthreads();
    float m = s_m, sc = s_scale;
    for (int i = threadIdx.x; i < N; i += blockDim.x) {
        float v = x[i];
        y[i] = (v - m) * sc + m;
    }
}

// ---------------- bf16 mma helpers ----------------
__device__ __forceinline__ void mma_bf16(float* c, uint32_t a0, uint32_t a1,
                                         uint32_t a2, uint32_t a3,
                                         uint32_t b0, uint32_t b1) {
    asm volatile(
        "mma.sync.aligned.m16n8k16.row.col.f32.bf16.bf16.f32 "
        "{%0,%1,%2,%3}, {%4,%5,%6,%7}, {%8,%9}, {%0,%1,%2,%3};"
        : "+f"(c[0]), "+f"(c[1]), "+f"(c[2]), "+f"(c[3])
        : "r"(a0), "r"(a1), "r"(a2), "r"(a3), "r"(b0), "r"(b1));
}

__device__ __forceinline__ uint32_t pack_bf16(float a, float b) {
    __nv_bfloat162 p = __floats2bfloat162_rn(a, b);
    return *reinterpret_cast<uint32_t*>(&p);
}

// ---------------- conv mma stage (one 64-k chunk into one buffer) ----------------
__device__ __forceinline__ void conv_mma_stage(
    const float* __restrict__ in, const float* __restrict__ wt,
    uint32_t* xs, uint32_t* ws, int k0, int h, int col0, int co0,
    int H, int W, size_t HW, int K, int wid, int lane)
{
    #pragma unroll
    for (int e = 0; e < 4; e++) {
        int kp = wid * 4 + e;
        int k  = k0 + kp * 2;
        int ci0 = k / 9, t0 = k - ci0 * 9;
        int di0 = t0 / 3, dj0 = t0 - di0 * 3;
        int k1 = k + 1;
        int ci1 = k1 / 9, t1 = k1 - ci1 * 9;
        int di1 = t1 / 3, dj1 = t1 - di1 * 3;
        int gh0 = h + di0 - 1, gh1 = h + di1 - 1;
        bool ok0 = (gh0 >= 0 && gh0 < H), ok1 = (gh1 >= 0 && gh1 < H);
        const float* ip0 = in + (size_t)ci0 * HW + (size_t)gh0 * W;
        const float* ip1 = in + (size_t)ci1 * HW + (size_t)gh1 * W;
        #pragma unroll
        for (int p4 = 0; p4 < 4; p4++) {
            int px = p4 * 32 + lane;
            int gw0 = col0 + px + dj0 - 1;
            int gw1 = col0 + px + dj1 - 1;
            float v0 = (ok0 && gw0 >= 0 && gw0 < W) ? ip0[gw0] : 0.f;
            float v1 = (ok1 && gw1 >= 0 && gw1 < W) ? ip1[gw1] : 0.f;
            xs[px * 36 + kp] = pack_bf16(v0, v1);
        }
    }
    #pragma unroll
    for (int i = 0; i < 16; i++) {
        int n = wid + 8 * i;
        const float* wp = wt + (size_t)(co0 + n) * K + k0 + 2 * lane;
        ws[n * 36 + lane] = pack_bf16(wp[0], wp[1]);
    }
}

// ---------------- bf16 mma implicit-GEMM 3x3 SAME conv (guide path), double-buffered ----------------
__global__ __launch_bounds__(256) void conv_mma_kernel(
    const float* __restrict__ in, const float* __restrict__ wt,
    const float* __restrict__ bias, float* __restrict__ out,
    int Cin, int H, int W)
{
    extern __shared__ uint32_t cms[];          // 2 buffers x (xs 4608 + ws 4608) u32
    const int tid = threadIdx.x, wid = tid >> 5, lane = tid & 31;
    const int h = blockIdx.y, col0 = blockIdx.x * 128;
    const int co0 = blockIdx.z * 128;
    const size_t HW = (size_t)H * W;
    const int K = Cin * 9;
    const int nch = K / 64;

    const int wm = wid & 3, wn = wid >> 2;
    const int m0 = wm * 32, n0 = wn * 64;

    float acc[2][8][4];
    #pragma unroll
    for (int mt = 0; mt < 2; mt++)
        #pragma unroll
        for (int nt = 0; nt < 8; nt++)
            #pragma unroll
            for (int r = 0; r < 4; r++) acc[mt][nt][r] = 0.f;

    conv_mma_stage(in, wt, cms, cms + 4608, 0, h, col0, co0, H, W, HW, K, wid, lane);
    __syncthreads();

    for (int ch = 0; ch < nch; ch++) {
        const int b = ch & 1;
        uint32_t* xs = cms + b * 9216;
        uint32_t* ws = cms + b * 9216 + 4608;

        if (ch + 1 < nch) {
            uint32_t* xs2 = cms + (b ^ 1) * 9216;
            conv_mma_stage(in, wt, xs2, xs2 + 4608, (ch + 1) * 64,
                           h, col0, co0, H, W, HW, K, wid, lane);
        }

        #pragma unroll
        for (int ks = 0; ks < 4; ks++) {
            int ar = lane >> 2, ac = ks * 8 + (lane & 3);
            uint32_t a[2][4];
            #pragma unroll
            for (int mt = 0; mt < 2; mt++) {
                int r = m0 + mt * 16 + ar;
                a[mt][0] = xs[r * 36 + ac];
                a[mt][1] = xs[(r + 8) * 36 + ac];
                a[mt][2] = xs[r * 36 + ac + 4];
                a[mt][3] = xs[(r + 8) * 36 + ac + 4];
            }
            #pragma unroll
            for (int nt = 0; nt < 8; nt++) {
                int n = n0 + nt * 8 + ar;
                uint32_t b0 = ws[n * 36 + ac];
                uint32_t b1 = ws[n * 36 + ac + 4];
                mma_bf16(acc[0][nt], a[0][0], a[0][1], a[0][2], a[0][3], b0, b1);
                mma_bf16(acc[1][nt], a[1][0], a[1][1], a[1][2], a[1][3], b0, b1);
            }
        }
        __syncthreads();
    }

    #pragma unroll
    for (int nt = 0; nt < 8; nt++) {
        int co = co0 + n0 + nt * 8 + 2 * (lane & 3);
        float bv0 = bias[co], bv1 = bias[co + 1];
        float* o0 = out + (size_t)co * HW + (size_t)h * W;
        float* o1 = out + (size_t)(co + 1) * HW + (size_t)h * W;
        #pragma unroll
        for (int mt = 0; mt < 2; mt++) {
            int px = col0 + m0 + mt * 16 + (lane >> 2);
            o0[px]     = acc[mt][nt][0] + bv0;
            o1[px]     = acc[mt][nt][1] + bv1;
            o0[px + 8] = acc[mt][nt][2] + bv0;
            o1[px + 8] = acc[mt][nt][3] + bv1;
        }
    }
}

// ---------------- pac GEMM stage (one 64-k chunk, split hi/lo) ----------------
__device__ __forceinline__ void pac_stage(
    const float* __restrict__ x, const float* __restrict__ wt,
    uint32_t* ah, uint32_t* al, uint32_t* bh, uint32_t* bl,
    int k0, int px0, int n0, int N, int M, int tid)
{
    #pragma unroll
    for (int i = 0; i < 16; i++) {
        int idx = tid + 256 * i;
        int px = idx & 127, kp = idx >> 7;
        const float* xp = x + (size_t)(k0 + 2 * kp) * M + px0 + px;
        float v0 = xp[0], v1 = xp[M];
        float h0 = __bfloat162float(__float2bfloat16_rn(v0));
        float h1 = __bfloat162float(__float2bfloat16_rn(v1));
        ah[px * 37 + kp] = pack_bf16(h0, h1);
        al[px * 37 + kp] = pack_bf16(v0 - h0, v1 - h1);
    }
    #pragma unroll
    for (int i = 0; i < 16; i++) {
        int idx = tid + 256 * i;
        int n = idx & 127, kp = idx >> 7;
        int gn = n0 + n;
        float v0 = 0.f, v1 = 0.f;
        if (gn < N) {
            const float* wp = wt + (size_t)(k0 + 2 * kp) * N + gn;
            v0 = wp[0]; v1 = wp[N];
        }
        float h0 = __bfloat162float(__float2bfloat16_rn(v0));
        float h1 = __bfloat162float(__float2bfloat16_rn(v1));
        bh[n * 37 + kp] = pack_bf16(h0, h1);
        bl[n * 37 + kp] = pack_bf16(v0 - h0, v1 - h1);
    }
}

// ---------------- split-bf16 GEMM for PAC (double-buffered) ----------------
// G[n][px] = sum_k x[k][px] * wt[k][n];  acc = xh*wh + xh*wl + xl*wh (fp32).
__global__ __launch_bounds__(256) void pac_gemm_kernel(
    const float* __restrict__ x, const float* __restrict__ wt,
    float* __restrict__ G, int Cin, int N, int M)
{
    extern __shared__ uint32_t sm[];           // 2 buffers x 4 tiles x 128*37 u32
    const int BUF = 18944, T = 4736;

    const int tid = threadIdx.x, wid = tid >> 5, lane = tid & 31;
    const int px0 = blockIdx.x * 128, n0 = blockIdx.y * 128;
    const int wm = wid & 3, wn = wid >> 2;
    const int m0 = wm * 32, nb0 = wn * 64;
    const int nch = Cin / 64;

    float acc[2][8][4];
    #pragma unroll
    for (int mt = 0; mt < 2; mt++)
        #pragma unroll
        for (int nt = 0; nt < 8; nt++)
            #pragma unroll
            for (int r = 0; r < 4; r++) acc[mt][nt][r] = 0.f;

    pac_stage(x, wt, sm, sm + T, sm + 2 * T, sm + 3 * T, 0, px0, n0, N, M, tid);
    __syncthreads();

    for (int ch = 0; ch < nch; ch++) {
        const int b = ch & 1;
        uint32_t* ah = sm + b * BUF;
        uint32_t* al = ah + T;
        uint32_t* bh = ah + 2 * T;
        uint32_t* bl = ah + 3 * T;

        if (ch + 1 < nch) {
            uint32_t* a2 = sm + (b ^ 1) * BUF;
            pac_stage(x, wt, a2, a2 + T, a2 + 2 * T, a2 + 3 * T,
                      (ch + 1) * 64, px0, n0, N, M, tid);
        }

        #pragma unroll
        for (int ks = 0; ks < 4; ks++) {
            int ar = lane >> 2, ac = ks * 8 + (lane & 3);
            uint32_t Ah[2][4], Al[2][4];
            #pragma unroll
            for (int mt = 0; mt < 2; mt++) {
                int r = m0 + mt * 16 + ar;
                Ah[mt][0] = ah[r * 37 + ac];
                Ah[mt][1] = ah[(r + 8) * 37 + ac];
                Ah[mt][2] = ah[r * 37 + ac + 4];
                Ah[mt][3] = ah[(r + 8) * 37 + ac + 4];
                Al[mt][0] = al[r * 37 + ac];
                Al[mt][1] = al[(r + 8) * 37 + ac];
                Al[mt][2] = al[r * 37 + ac + 4];
                Al[mt][3] = al[(r + 8) * 37 + ac + 4];
            }
            #pragma unroll
            for (int nt = 0; nt < 8; nt++) {
                int n = nb0 + nt * 8 + ar;
                uint32_t bh0 = bh[n * 37 + ac], bh1 = bh[n * 37 + ac + 4];
                uint32_t bl0 = bl[n * 37 + ac], bl1 = bl[n * 37 + ac + 4];
                mma_bf16(acc[0][nt], Ah[0][0], Ah[0][1], Ah[0][2], Ah[0][3], bh0, bh1);
                mma_bf16(acc[1][nt], Ah[1][0], Ah[1][1], Ah[1][2], Ah[1][3], bh0, bh1);
                mma_bf16(acc[0][nt], Ah[0][0], Ah[0][1], Ah[0][2], Ah[0][3], bl0, bl1);
                mma_bf16(acc[1][nt], Ah[1][0], Ah[1][1], Ah[1][2], Ah[1][3], bl0, bl1);
                mma_bf16(acc[0][nt], Al[0][0], Al[0][1], Al[0][2], Al[0][3], bh0, bh1);
                mma_bf16(acc[1][nt], Al[1][0], Al[1][1], Al[1][2], Al[1][3], bh0, bh1);
            }
        }
        __syncthreads();
    }

    #pragma unroll
    for (int nt = 0; nt < 8; nt++) {
        int n = n0 + nb0 + nt * 8 + 2 * (lane & 3);
        #pragma unroll
        for (int mt = 0; mt < 2; mt++) {
            int px = px0 + m0 + mt * 16 + (lane >> 2);
            if (n < N) {
                G[(size_t)n * M + px]     = acc[mt][nt][0];
                G[(size_t)n * M + px + 8] = acc[mt][nt][2];
            }
            if (n + 1 < N) {
                G[(size_t)(n + 1) * M + px]     = acc[mt][nt][1];
                G[(size_t)(n + 1) * M + px + 8] = acc[mt][nt][3];
            }
        }
    }
}

// ---------------- PAC apply: gather G planes through kk ----------------
__global__ __launch_bounds__(128) void pac_apply_kernel(
    const float* __restrict__ G, const float* __restrict__ kk,
    const float* __restrict__ bias, float* __restrict__ out,
    int H, int W)
{
    const int s = blockIdx.x * 32 + (threadIdx.x & 31);
    const int r = blockIdx.y * 4 + (threadIdx.x >> 5);
    const int co = blockIdx.z;
    const size_t M = (size_t)H * W;
    const size_t base = (size_t)r * W + s;
    const float* gp = G + (size_t)co * 9 * M;
    const bool sr = (s + 1 < W), rd = (r + 1 < H);
    const int Wo = 2 * W;
    const size_t HWo = 4 * M;
    const size_t b00 = (size_t)(2 * r) * Wo + 2 * s;
    const size_t b10 = b00 + Wo;
    const float bv = bias[co];

    float o00 = bv + kk[4 * HWo + b00] * gp[4 * M + base];
    float o01 = bv + kk[3 * HWo + b00 + 1] * gp[3 * M + base]
              + (sr ? kk[5 * HWo + b00 + 1] * gp[5 * M + base + 1] : 0.f);
    float o10 = bv + kk[1 * HWo + b10] * gp[1 * M + base]
              + (rd ? kk[7 * HWo + b10] * gp[7 * M + base + W] : 0.f);
    float o11 = bv + kk[0 * HWo + b10 + 1] * gp[0 * M + base]
              + (sr ? kk[2 * HWo + b10 + 1] * gp[2 * M + base + 1] : 0.f)
              + (rd ? kk[6 * HWo + b10 + 1] * gp[6 * M + base + W] : 0.f)
              + ((sr && rd) ? kk[8 * HWo + b10 + 1] * gp[8 * M + base + W + 1] : 0.f);

    float* op = out + (size_t)co * HWo;
    op[b00] = o00; op[b00 + 1] = o01;
    op[b10] = o10; op[b10 + 1] = o11;
}

// ---------------- final conv 64->3: single-barrier full-channel staging ----------------
__global__ __launch_bounds__(96) void conv_out_kernel(
    const float* __restrict__ in, const float* __restrict__ wt,
    const float* __restrict__ bias, float* __restrict__ out, int H, int W)
{
    extern __shared__ float s[];
    float* xs = s;                 // [64][6*36]
    float* ws = s + 64 * 216;      // [3*64*9] = wt verbatim
    const int tx = threadIdx.x, ty = threadIdx.y, co = threadIdx.z;
    const int tid = tx + 8 * (ty + 4 * co);
    const int w0 = blockIdx.x * 32, h0 = blockIdx.y * 4;
    const size_t HW = (size_t)H * W;

    for (int i = tid; i < 1728; i += 96) ws[i] = wt[i];
    for (int i = tid; i < 64 * 210; i += 96) {
        int ci = i / 210, rem = i - ci * 210;
        int r = rem / 35, c = rem - r * 35;
        int gh = h0 + r - 1, gw = w0 + c - 1;
        float v = (gh >= 0 && gh < H && gw >= 0 && gw < W) ? in[(size_t)ci * HW + (size_t)gh * W + gw] : 0.f;
        xs[ci * 216 + r * 36 + c] = v;
    }
    __syncthreads();

    float acc[4] = {0.f, 0.f, 0.f, 0.f};
    const float* wp = ws + co * 576;
    for (int ci = 0; ci < 64; ci++) {
        const float* xp = xs + ci * 216;
        const float* wc = wp + ci * 9;
        #pragma unroll
        for (int di = 0; di < 3; di++) {
            float4 x4 = *(const float4*)&xp[(ty + di) * 36 + tx * 4];
            float x5 = xp[(ty + di) * 36 + tx * 4 + 4];
            float x6 = xp[(ty + di) * 36 + tx * 4 + 5];
            float xr[6] = {x4.x, x4.y, x4.z, x4.w, x5, x6};
            float wr0 = wc[di * 3], wr1 = wc[di * 3 + 1], wr2 = wc[di * 3 + 2];
            #pragma unroll
            for (int p = 0; p < 4; p++)
                acc[p] += xr[p] * wr0 + xr[p + 1] * wr1 + xr[p + 2] * wr2;
        }
    }

    float bv = bias[co];
    float* op = out + (size_t)co * HW + (size_t)(h0 + ty) * W + w0 + tx * 4;
    #pragma unroll
    for (int p = 0; p < 4; p++) op[p] = acc[p] + bv;
}

// ---------------- guide kernel: barrier-free, one thread per pixel ----------------
__global__ __launch_bounds__(128) void kk_kernel(const float* __restrict__ g,
                                                 float* __restrict__ kk,
                                                 int Cg, int H, int W) {
    const int tx = threadIdx.x & 31, ty = threadIdx.x >> 5;
    const int w = blockIdx.x * 32 + tx;
    const int h = blockIdx.y * 4 + ty;
    const size_t HW = (size_t)H * W;

    const bool bl = (w > 0), br = (w < W - 1), bu = (h > 0), bd = (h < H - 1);
    const float* p = g + (size_t)h * W + w;

    float a0 = 0.f, a1 = 0.f, a2 = 0.f, a3 = 0.f,
          a5 = 0.f, a6 = 0.f, a7 = 0.f, a8 = 0.f;

    for (int c = 0; c + 2 <= Cg; c += 2, p += 2 * HW) {
        {
            float ctr = p[0];
            float v0 = (bu && bl) ? p[-W - 1] : 0.f;
            float v1 = bu ? p[-W] : 0.f;
            float v2 = (bu && br) ? p[-W + 1] : 0.f;
            float v3 = bl ? p[-1] : 0.f;
            float v5 = br ? p[1] : 0.f;
            float v6 = (bd && bl) ? p[W - 1] : 0.f;
            float v7 = bd ? p[W] : 0.f;
            float v8 = (bd && br) ? p[W + 1] : 0.f;
            float d0 = v0 - ctr; a0 += d0 * d0;
            float d1 = v1 - ctr; a1 += d1 * d1;
            float d2 = v2 - ctr; a2 += d2 * d2;
            float d3 = v3 - ctr; a3 += d3 * d3;
            float d5 = v5 - ctr; a5 += d5 * d5;
            float d6 = v6 - ctr; a6 += d6 * d6;
            float d7 = v7 - ctr; a7 += d7 * d7;
            float d8 = v8 - ctr; a8 += d8 * d8;
        }
        {
            const float* q = p + HW;
            float ctr = q[0];
            float v0 = (bu && bl) ? q[-W - 1] : 0.f;
            float v1 = bu ? q[-W] : 0.f;
            float v2 = (bu && br) ? q[-W + 1] : 0.f;
            float v3 = bl ? q[-1] : 0.f;
            float v5 = br ? q[1] : 0.f;
            float v6 = (bd && bl) ? q[W - 1] : 0.f;
            float v7 = bd ? q[W] : 0.f;
            float v8 = (bd && br) ? q[W + 1] : 0.f;
            float d0 = v0 - ctr; a0 += d0 * d0;
            float d1 = v1 - ctr; a1 += d1 * d1;
            float d2 = v2 - ctr; a2 += d2 * d2;
            float d3 = v3 - ctr; a3 += d3 * d3;
            float d5 = v5 - ctr; a5 += d5 * d5;
            float d6 = v6 - ctr; a6 += d6 * d6;
            float d7 = v7 - ctr; a7 += d7 * d7;
            float d8 = v8 - ctr; a8 += d8 * d8;
        }
    }

    size_t o = (size_t)h * W + w;
    kk[0 * HW + o] = expf(-0.5f * a0);
    kk[1 * HW + o] = expf(-0.5f * a1);
    kk[2 * HW + o] = expf(-0.5f * a2);
    kk[3 * HW + o] = expf(-0.5f * a3);
    kk[4 * HW + o] = 1.0f;
    kk[5 * HW + o] = expf(-0.5f * a5);
    kk[6 * HW + o] = expf(-0.5f * a6);
    kk[7 * HW + o] = expf(-0.5f * a7);
    kk[8 * HW + o] = expf(-0.5f * a8);
}

// ---------------- launch ----------------
extern "C" void kernel_launch(void* const* d_in, const int* in_sizes, int n_in,
                              void* d_out, int out_size) {
    const float* x       = (const float*)d_in[0];
    const float* ef_lv2  = (const float*)d_in[1];
    const float* ef_lv1  = (const float*)d_in[2];
    const float* w_adj2  = (const float*)d_in[3];
    const float* b_adj2  = (const float*)d_in[4];
    const float* w_adj1  = (const float*)d_in[5];
    const float* b_adj1  = (const float*)d_in[6];
    const float* w_pac16 = (const float*)d_in[7];
    const float* b_pac16 = (const float*)d_in[8];
    const float* w_pac20 = (const float*)d_in[9];
    const float* b_pac20 = (const float*)d_in[10];
    const float* w_out   = (const float*)d_in[11];
    const float* b_out   = (const float*)d_in[12];
    float* outp = (float*)d_out;

    float *xA, *g2, *kk1, *xB, *g1, *kk2, *xC, *G;
    cudaGetSymbolAddress((void**)&xA,  g_xA);
    cudaGetSymbolAddress((void**)&g2,  g_g2);
    cudaGetSymbolAddress((void**)&kk1, g_kk1);
    cudaGetSymbolAddress((void**)&xB,  g_xB);
    cudaGetSymbolAddress((void**)&g1,  g_g1);
    cudaGetSymbolAddress((void**)&kk2, g_kk2);
    cudaGetSymbolAddress((void**)&xC,  g_xC);
    cudaGetSymbolAddress((void**)&G,   g_G);

    const int SMEM_PG = 2 * 4 * 128 * 37 * 4;     // 151552 B
    const int SMEM_CM = 2 * 2 * 128 * 36 * 4;     // 73728 B
    const int SMEM_CO = (64 * 216 + 1728) * 4;    // 62208 B
    cudaFuncSetAttribute(pac_gemm_kernel, cudaFuncAttributeMaxDynamicSharedMemorySize, SMEM_PG);
    cudaFuncSetAttribute(conv_mma_kernel, cudaFuncAttributeMaxDynamicSharedMemorySize, SMEM_CM);
    cudaFuncSetAttribute(conv_out_kernel, cudaFuncAttributeMaxDynamicSharedMemorySize, SMEM_CO);

    // stage 1: collapsed double inorm-residual (256, 64, 64)
    dinorm_kernel<<<256, 256>>>(x, xA, 64 * 64);

    // g2 = conv3x3(ef_lv2; 128->256 @128x128)
    conv_mma_kernel<<<dim3(1, 128, 2), 256, SMEM_CM>>>(ef_lv2, w_adj2, b_adj2, g2, 128, 128, 128);

    // kk1 from g2
    kk_kernel<<<dim3(4, 32), 128>>>(g2, kk1, 256, 128, 128);

    // pac1: GEMM (M=4096, N=1152, K=256) + apply -> xB (128,128,128)
    pac_gemm_kernel<<<dim3(32, 9), 256, SMEM_PG>>>(xA, w_pac16, G, 256, 1152, 4096);
    pac_apply_kernel<<<dim3(2, 16, 128), 128>>>(G, kk1, b_pac16, xB, 64, 64);

    dinorm_kernel<<<128, 256>>>(xB, xB, 128 * 128);

    // g1 = conv3x3(ef_lv1; 64->128 @256x256)
    conv_mma_kernel<<<dim3(2, 256, 1), 256, SMEM_CM>>>(ef_lv1, w_adj1, b_adj1, g1, 64, 256, 256);

    // kk2 from g1
    kk_kernel<<<dim3(8, 64), 128>>>(g1, kk2, 128, 256, 256);

    // pac2: GEMM (M=16384, N=576, K=128) + apply -> xC (64,256,256)
    pac_gemm_kernel<<<dim3(128, 5), 256, SMEM_PG>>>(xB, w_pac20, G, 128, 576, 16384);
    pac_apply_kernel<<<dim3(4, 32, 64), 128>>>(G, kk2, b_pac20, xC, 128, 128);

    dinorm_kernel<<<64, 256>>>(xC, xC, 256 * 256);

    // final conv: 64->3 @256x256 (single-barrier, fp32)
    conv_out_kernel<<<dim3(8, 64), dim3(8, 4, 3), SMEM_CO>>>(xC, w_out, b_out, outp, 256, 256);
}

// round 15
// speedup vs baseline: 1.2387x; 1.2387x over previous
#include <cuda_runtime.h>
#include <cuda_bf16.h>
#include <math.h>
#include <cstdint>

#define EPS 1e-5f

// ---------------- scratch (static device globals) ----------------
__device__ float g_xA [256*64*64];
__device__ float g_g2 [256*128*128];
__device__ float g_kk1[9*128*128];
__device__ float g_xB [128*128*128];
__device__ float g_g1 [128*256*256];
__device__ float g_kk2[9*256*256];
__device__ float g_xC [64*256*256];
__device__ float g_G  [9437184];       // pac GEMM output, max 576*16384 floats (36 MB)

// ---------------- double instance-norm residual (512 threads) ----------------
__global__ void dinorm_kernel(const float* __restrict__ in, float* __restrict__ out, int N) {
    const int c = blockIdx.x;
    const float* x = in + (size_t)c * N;
    float* y = out + (size_t)c * N;

    float s = 0.f, s2 = 0.f;
    for (int i = threadIdx.x; i < N; i += blockDim.x) {
        float v = x[i];
        s += v; s2 += v * v;
    }
    #pragma unroll
    for (int o = 16; o > 0; o >>= 1) {
        s  += __shfl_down_sync(0xffffffffu, s,  o);
        s2 += __shfl_down_sync(0xffffffffu, s2, o);
    }
    __shared__ float redA[32], redB[32];
    __shared__ float s_m, s_scale;
    int wid = threadIdx.x >> 5, lid = threadIdx.x & 31;
    if (lid == 0) { redA[wid] = s; redB[wid] = s2; }
    __syncthreads();
    if (threadIdx.x == 0) {
        float S = 0.f, S2 = 0.f;
        int nw = blockDim.x >> 5;
        for (int i = 0; i < nw; i++) { S += redA[i]; S2 += redB[i]; }
        float m = S / N;
        float v = S2 / N - m * m;
        if (v < 0.f) v = 0.f;
        float r  = rsqrtf(v + EPS);
        float r2 = rsqrtf(v * (1.f + r) * (1.f + r) + EPS);
        s_m = m; s_scale = (1.f + r) * (1.f + r2);
    }
    __syncthreads();
    float m = s_m, sc = s_scale;
    for (int i = threadIdx.x; i < N; i += blockDim.x) {
        float v = x[i];
        y[i] = (v - m) * sc + m;
    }
}

// ---------------- bf16 mma helpers ----------------
__device__ __forceinline__ void mma_bf16(float* c, uint32_t a0, uint32_t a1,
                                         uint32_t a2, uint32_t a3,
                                         uint32_t b0, uint32_t b1) {
    asm volatile(
        "mma.sync.aligned.m16n8k16.row.col.f32.bf16.bf16.f32 "
        "{%0,%1,%2,%3}, {%4,%5,%6,%7}, {%8,%9}, {%0,%1,%2,%3};"
        : "+f"(c[0]), "+f"(c[1]), "+f"(c[2]), "+f"(c[3])
        : "r"(a0), "r"(a1), "r"(a2), "r"(a3), "r"(b0), "r"(b1));
}

__device__ __forceinline__ uint32_t pack_bf16(float a, float b) {
    __nv_bfloat162 p = __floats2bfloat162_rn(a, b);
    return *reinterpret_cast<uint32_t*>(&p);
}

// ---------------- bf16 mma implicit-GEMM 3x3 SAME conv (guide path, R10 single-buffer) ----------------
__global__ __launch_bounds__(256) void conv_mma_kernel(
    const float* __restrict__ in, const float* __restrict__ wt,
    const float* __restrict__ bias, float* __restrict__ out,
    int Cin, int H, int W)
{
    const int PITCH = 36;
    __shared__ uint32_t xs[128 * PITCH];
    __shared__ uint32_t ws[128 * PITCH];

    const int tid = threadIdx.x, wid = tid >> 5, lane = tid & 31;
    const int h = blockIdx.y, col0 = blockIdx.x * 128;
    const int co0 = blockIdx.z * 128;
    const size_t HW = (size_t)H * W;
    const int K = Cin * 9;
    const int nch = K / 64;

    const int wm = wid & 3, wn = wid >> 2;
    const int m0 = wm * 32, n0 = wn * 64;

    float acc[2][8][4];
    #pragma unroll
    for (int mt = 0; mt < 2; mt++)
        #pragma unroll
        for (int nt = 0; nt < 8; nt++)
            #pragma unroll
            for (int r = 0; r < 4; r++) acc[mt][nt][r] = 0.f;

    for (int ch = 0; ch < nch; ch++) {
        const int k0 = ch * 64;

        #pragma unroll
        for (int e = 0; e < 4; e++) {
            int kp = wid * 4 + e;
            int k  = k0 + kp * 2;
            int ci0 = k / 9, t0 = k - ci0 * 9;
            int di0 = t0 / 3, dj0 = t0 - di0 * 3;
            int k1 = k + 1;
            int ci1 = k1 / 9, t1 = k1 - ci1 * 9;
            int di1 = t1 / 3, dj1 = t1 - di1 * 3;
            int gh0 = h + di0 - 1, gh1 = h + di1 - 1;
            bool ok0 = (gh0 >= 0 && gh0 < H), ok1 = (gh1 >= 0 && gh1 < H);
            const float* ip0 = in + (size_t)ci0 * HW + (size_t)gh0 * W;
            const float* ip1 = in + (size_t)ci1 * HW + (size_t)gh1 * W;
            #pragma unroll
            for (int p4 = 0; p4 < 4; p4++) {
                int px = p4 * 32 + lane;
                int gw0 = col0 + px + dj0 - 1;
                int gw1 = col0 + px + dj1 - 1;
                float v0 = (ok0 && gw0 >= 0 && gw0 < W) ? ip0[gw0] : 0.f;
                float v1 = (ok1 && gw1 >= 0 && gw1 < W) ? ip1[gw1] : 0.f;
                xs[px * PITCH + kp] = pack_bf16(v0, v1);
            }
        }
        #pragma unroll
        for (int i = 0; i < 16; i++) {
            int n = wid + 8 * i;
            const float* wp = wt + (size_t)(co0 + n) * K + k0 + 2 * lane;
            ws[n * PITCH + lane] = pack_bf16(wp[0], wp[1]);
        }
        __syncthreads();

        #pragma unroll
        for (int ks = 0; ks < 4; ks++) {
            int ar = lane >> 2, ac = ks * 8 + (lane & 3);
            uint32_t a[2][4];
            #pragma unroll
            for (int mt = 0; mt < 2; mt++) {
                int r = m0 + mt * 16 + ar;
                a[mt][0] = xs[r * PITCH + ac];
                a[mt][1] = xs[(r + 8) * PITCH + ac];
                a[mt][2] = xs[r * PITCH + ac + 4];
                a[mt][3] = xs[(r + 8) * PITCH + ac + 4];
            }
            #pragma unroll
            for (int nt = 0; nt < 8; nt++) {
                int n = n0 + nt * 8 + ar;
                uint32_t b0 = ws[n * PITCH + ac];
                uint32_t b1 = ws[n * PITCH + ac + 4];
                mma_bf16(acc[0][nt], a[0][0], a[0][1], a[0][2], a[0][3], b0, b1);
                mma_bf16(acc[1][nt], a[1][0], a[1][1], a[1][2], a[1][3], b0, b1);
            }
        }
        __syncthreads();
    }

    #pragma unroll
    for (int nt = 0; nt < 8; nt++) {
        int co = co0 + n0 + nt * 8 + 2 * (lane & 3);
        float bv0 = bias[co], bv1 = bias[co + 1];
        float* o0 = out + (size_t)co * HW + (size_t)h * W;
        float* o1 = out + (size_t)(co + 1) * HW + (size_t)h * W;
        #pragma unroll
        for (int mt = 0; mt < 2; mt++) {
            int px = col0 + m0 + mt * 16 + (lane >> 2);
            o0[px]     = acc[mt][nt][0] + bv0;
            o1[px]     = acc[mt][nt][1] + bv1;
            o0[px + 8] = acc[mt][nt][2] + bv0;
            o1[px + 8] = acc[mt][nt][3] + bv1;
        }
    }
}

// ---------------- split-bf16 GEMM for PAC (R10 single-buffer) ----------------
// G[n][px] = sum_k x[k][px] * wt[k][n];  acc = xh*wh + xh*wl + xl*wh (fp32).
__global__ __launch_bounds__(256) void pac_gemm_kernel(
    const float* __restrict__ x, const float* __restrict__ wt,
    float* __restrict__ G, int Cin, int N, int M)
{
    const int P = 37;
    extern __shared__ uint32_t sm[];
    uint32_t* ah = sm;
    uint32_t* al = ah + 128 * P;
    uint32_t* bh = al + 128 * P;
    uint32_t* bl = bh + 128 * P;

    const int tid = threadIdx.x, wid = tid >> 5, lane = tid & 31;
    const int px0 = blockIdx.x * 128, n0 = blockIdx.y * 128;
    const int wm = wid & 3, wn = wid >> 2;
    const int m0 = wm * 32, nb0 = wn * 64;
    const int nch = Cin / 64;

    float acc[2][8][4];
    #pragma unroll
    for (int mt = 0; mt < 2; mt++)
        #pragma unroll
        for (int nt = 0; nt < 8; nt++)
            #pragma unroll
            for (int r = 0; r < 4; r++) acc[mt][nt][r] = 0.f;

    for (int ch = 0; ch < nch; ch++) {
        const int k0 = ch * 64;

        #pragma unroll
        for (int i = 0; i < 16; i++) {
            int idx = tid + 256 * i;
            int px = idx & 127, kp = idx >> 7;
            const float* xp = x + (size_t)(k0 + 2 * kp) * M + px0 + px;
            float v0 = xp[0], v1 = xp[M];
            float h0 = __bfloat162float(__float2bfloat16_rn(v0));
            float h1 = __bfloat162float(__float2bfloat16_rn(v1));
            ah[px * P + kp] = pack_bf16(h0, h1);
            al[px * P + kp] = pack_bf16(v0 - h0, v1 - h1);
        }
        #pragma unroll
        for (int i = 0; i < 16; i++) {
            int idx = tid + 256 * i;
            int n = idx & 127, kp = idx >> 7;
            int gn = n0 + n;
            float v0 = 0.f, v1 = 0.f;
            if (gn < N) {
                const float* wp = wt + (size_t)(k0 + 2 * kp) * N + gn;
                v0 = wp[0]; v1 = wp[N];
            }
            float h0 = __bfloat162float(__float2bfloat16_rn(v0));
            float h1 = __bfloat162float(__float2bfloat16_rn(v1));
            bh[n * P + kp] = pack_bf16(h0, h1);
            bl[n * P + kp] = pack_bf16(v0 - h0, v1 - h1);
        }
        __syncthreads();

        #pragma unroll
        for (int ks = 0; ks < 4; ks++) {
            int ar = lane >> 2, ac = ks * 8 + (lane & 3);
            uint32_t Ah[2][4], Al[2][4];
            #pragma unroll
            for (int mt = 0; mt < 2; mt++) {
                int r = m0 + mt * 16 + ar;
                Ah[mt][0] = ah[r * P + ac];
                Ah[mt][1] = ah[(r + 8) * P + ac];
                Ah[mt][2] = ah[r * P + ac + 4];
                Ah[mt][3] = ah[(r + 8) * P + ac + 4];
                Al[mt][0] = al[r * P + ac];
                Al[mt][1] = al[(r + 8) * P + ac];
                Al[mt][2] = al[r * P + ac + 4];
                Al[mt][3] = al[(r + 8) * P + ac + 4];
            }
            #pragma unroll
            for (int nt = 0; nt < 8; nt++) {
                int n = nb0 + nt * 8 + ar;
                uint32_t bh0 = bh[n * P + ac], bh1 = bh[n * P + ac + 4];
                uint32_t bl0 = bl[n * P + ac], bl1 = bl[n * P + ac + 4];
                mma_bf16(acc[0][nt], Ah[0][0], Ah[0][1], Ah[0][2], Ah[0][3], bh0, bh1);
                mma_bf16(acc[1][nt], Ah[1][0], Ah[1][1], Ah[1][2], Ah[1][3], bh0, bh1);
                mma_bf16(acc[0][nt], Ah[0][0], Ah[0][1], Ah[0][2], Ah[0][3], bl0, bl1);
                mma_bf16(acc[1][nt], Ah[1][0], Ah[1][1], Ah[1][2], Ah[1][3], bl0, bl1);
                mma_bf16(acc[0][nt], Al[0][0], Al[0][1], Al[0][2], Al[0][3], bh0, bh1);
                mma_bf16(acc[1][nt], Al[1][0], Al[1][1], Al[1][2], Al[1][3], bh0, bh1);
            }
        }
        __syncthreads();
    }

    #pragma unroll
    for (int nt = 0; nt < 8; nt++) {
        int n = n0 + nb0 + nt * 8 + 2 * (lane & 3);
        #pragma unroll
        for (int mt = 0; mt < 2; mt++) {
            int px = px0 + m0 + mt * 16 + (lane >> 2);
            if (n < N) {
                G[(size_t)n * M + px]     = acc[mt][nt][0];
                G[(size_t)n * M + px + 8] = acc[mt][nt][2];
            }
            if (n + 1 < N) {
                G[(size_t)(n + 1) * M + px]     = acc[mt][nt][1];
                G[(size_t)(n + 1) * M + px + 8] = acc[mt][nt][3];
            }
        }
    }
}

// ---------------- PAC apply: gather G planes through kk ----------------
__global__ __launch_bounds__(128) void pac_apply_kernel(
    const float* __restrict__ G, const float* __restrict__ kk,
    const float* __restrict__ bias, float* __restrict__ out,
    int H, int W)
{
    const int s = blockIdx.x * 32 + (threadIdx.x & 31);
    const int r = blockIdx.y * 4 + (threadIdx.x >> 5);
    const int co = blockIdx.z;
    const size_t M = (size_t)H * W;
    const size_t base = (size_t)r * W + s;
    const float* gp = G + (size_t)co * 9 * M;
    const bool sr = (s + 1 < W), rd = (r + 1 < H);
    const int Wo = 2 * W;
    const size_t HWo = 4 * M;
    const size_t b00 = (size_t)(2 * r) * Wo + 2 * s;
    const size_t b10 = b00 + Wo;
    const float bv = bias[co];

    float o00 = bv + kk[4 * HWo + b00] * gp[4 * M + base];
    float o01 = bv + kk[3 * HWo + b00 + 1] * gp[3 * M + base]
              + (sr ? kk[5 * HWo + b00 + 1] * gp[5 * M + base + 1] : 0.f);
    float o10 = bv + kk[1 * HWo + b10] * gp[1 * M + base]
              + (rd ? kk[7 * HWo + b10] * gp[7 * M + base + W] : 0.f);
    float o11 = bv + kk[0 * HWo + b10 + 1] * gp[0 * M + base]
              + (sr ? kk[2 * HWo + b10 + 1] * gp[2 * M + base + 1] : 0.f)
              + (rd ? kk[6 * HWo + b10 + 1] * gp[6 * M + base + W] : 0.f)
              + ((sr && rd) ? kk[8 * HWo + b10 + 1] * gp[8 * M + base + W + 1] : 0.f);

    float* op = out + (size_t)co * HWo;
    op[b00] = o00; op[b00 + 1] = o01;
    op[b10] = o10; op[b10 + 1] = o11;
}

// ---------------- final conv 64->3: single-barrier full-channel staging ----------------
__global__ __launch_bounds__(96) void conv_out_kernel(
    const float* __restrict__ in, const float* __restrict__ wt,
    const float* __restrict__ bias, float* __restrict__ out, int H, int W)
{
    extern __shared__ float s[];
    float* xs = s;                 // [64][6*36]
    float* ws = s + 64 * 216;      // [3*64*9] = wt verbatim
    const int tx = threadIdx.x, ty = threadIdx.y, co = threadIdx.z;
    const int tid = tx + 8 * (ty + 4 * co);
    const int w0 = blockIdx.x * 32, h0 = blockIdx.y * 4;
    const size_t HW = (size_t)H * W;

    for (int i = tid; i < 1728; i += 96) ws[i] = wt[i];
    for (int i = tid; i < 64 * 210; i += 96) {
        int ci = i / 210, rem = i - ci * 210;
        int r = rem / 35, c = rem - r * 35;
        int gh = h0 + r - 1, gw = w0 + c - 1;
        float v = (gh >= 0 && gh < H && gw >= 0 && gw < W) ? in[(size_t)ci * HW + (size_t)gh * W + gw] : 0.f;
        xs[ci * 216 + r * 36 + c] = v;
    }
    __syncthreads();

    float acc[4] = {0.f, 0.f, 0.f, 0.f};
    const float* wp = ws + co * 576;
    for (int ci = 0; ci < 64; ci++) {
        const float* xp = xs + ci * 216;
        const float* wc = wp + ci * 9;
        #pragma unroll
        for (int di = 0; di < 3; di++) {
            float4 x4 = *(const float4*)&xp[(ty + di) * 36 + tx * 4];
            float x5 = xp[(ty + di) * 36 + tx * 4 + 4];
            float x6 = xp[(ty + di) * 36 + tx * 4 + 5];
            float xr[6] = {x4.x, x4.y, x4.z, x4.w, x5, x6};
            float wr0 = wc[di * 3], wr1 = wc[di * 3 + 1], wr2 = wc[di * 3 + 2];
            #pragma unroll
            for (int p = 0; p < 4; p++)
                acc[p] += xr[p] * wr0 + xr[p + 1] * wr1 + xr[p + 2] * wr2;
        }
    }

    float bv = bias[co];
    float* op = out + (size_t)co * HW + (size_t)(h0 + ty) * W + w0 + tx * 4;
    #pragma unroll
    for (int p = 0; p < 4; p++) op[p] = acc[p] + bv;
}

// ---------------- guide kernel: barrier-free, one thread per pixel ----------------
__global__ __launch_bounds__(128) void kk_kernel(const float* __restrict__ g,
                                                 float* __restrict__ kk,
                                                 int Cg, int H, int W) {
    const int tx = threadIdx.x & 31, ty = threadIdx.x >> 5;
    const int w = blockIdx.x * 32 + tx;
    const int h = blockIdx.y * 4 + ty;
    const size_t HW = (size_t)H * W;

    const bool bl = (w > 0), br = (w < W - 1), bu = (h > 0), bd = (h < H - 1);
    const float* p = g + (size_t)h * W + w;

    float a0 = 0.f, a1 = 0.f, a2 = 0.f, a3 = 0.f,
          a5 = 0.f, a6 = 0.f, a7 = 0.f, a8 = 0.f;

    for (int c = 0; c + 2 <= Cg; c += 2, p += 2 * HW) {
        {
            float ctr = p[0];
            float v0 = (bu && bl) ? p[-W - 1] : 0.f;
            float v1 = bu ? p[-W] : 0.f;
            float v2 = (bu && br) ? p[-W + 1] : 0.f;
            float v3 = bl ? p[-1] : 0.f;
            float v5 = br ? p[1] : 0.f;
            float v6 = (bd && bl) ? p[W - 1] : 0.f;
            float v7 = bd ? p[W] : 0.f;
            float v8 = (bd && br) ? p[W + 1] : 0.f;
            float d0 = v0 - ctr; a0 += d0 * d0;
            float d1 = v1 - ctr; a1 += d1 * d1;
            float d2 = v2 - ctr; a2 += d2 * d2;
            float d3 = v3 - ctr; a3 += d3 * d3;
            float d5 = v5 - ctr; a5 += d5 * d5;
            float d6 = v6 - ctr; a6 += d6 * d6;
            float d7 = v7 - ctr; a7 += d7 * d7;
            float d8 = v8 - ctr; a8 += d8 * d8;
        }
        {
            const float* q = p + HW;
            float ctr = q[0];
            float v0 = (bu && bl) ? q[-W - 1] : 0.f;
            float v1 = bu ? q[-W] : 0.f;
            float v2 = (bu && br) ? q[-W + 1] : 0.f;
            float v3 = bl ? q[-1] : 0.f;
            float v5 = br ? q[1] : 0.f;
            float v6 = (bd && bl) ? q[W - 1] : 0.f;
            float v7 = bd ? q[W] : 0.f;
            float v8 = (bd && br) ? q[W + 1] : 0.f;
            float d0 = v0 - ctr; a0 += d0 * d0;
            float d1 = v1 - ctr; a1 += d1 * d1;
            float d2 = v2 - ctr; a2 += d2 * d2;
            float d3 = v3 - ctr; a3 += d3 * d3;
            float d5 = v5 - ctr; a5 += d5 * d5;
            float d6 = v6 - ctr; a6 += d6 * d6;
            float d7 = v7 - ctr; a7 += d7 * d7;
            float d8 = v8 - ctr; a8 += d8 * d8;
        }
    }

    size_t o = (size_t)h * W + w;
    kk[0 * HW + o] = expf(-0.5f * a0);
    kk[1 * HW + o] = expf(-0.5f * a1);
    kk[2 * HW + o] = expf(-0.5f * a2);
    kk[3 * HW + o] = expf(-0.5f * a3);
    kk[4 * HW + o] = 1.0f;
    kk[5 * HW + o] = expf(-0.5f * a5);
    kk[6 * HW + o] = expf(-0.5f * a6);
    kk[7 * HW + o] = expf(-0.5f * a7);
    kk[8 * HW + o] = expf(-0.5f * a8);
}

// ---------------- launch ----------------
extern "C" void kernel_launch(void* const* d_in, const int* in_sizes, int n_in,
                              void* d_out, int out_size) {
    const float* x       = (const float*)d_in[0];
    const float* ef_lv2  = (const float*)d_in[1];
    const float* ef_lv1  = (const float*)d_in[2];
    const float* w_adj2  = (const float*)d_in[3];
    const float* b_adj2  = (const float*)d_in[4];
    const float* w_adj1  = (const float*)d_in[5];
    const float* b_adj1  = (const float*)d_in[6];
    const float* w_pac16 = (const float*)d_in[7];
    const float* b_pac16 = (const float*)d_in[8];
    const float* w_pac20 = (const float*)d_in[9];
    const float* b_pac20 = (const float*)d_in[10];
    const float* w_out   = (const float*)d_in[11];
    const float* b_out   = (const float*)d_in[12];
    float* outp = (float*)d_out;

    float *xA, *g2, *kk1, *xB, *g1, *kk2, *xC, *G;
    cudaGetSymbolAddress((void**)&xA,  g_xA);
    cudaGetSymbolAddress((void**)&g2,  g_g2);
    cudaGetSymbolAddress((void**)&kk1, g_kk1);
    cudaGetSymbolAddress((void**)&xB,  g_xB);
    cudaGetSymbolAddress((void**)&g1,  g_g1);
    cudaGetSymbolAddress((void**)&kk2, g_kk2);
    cudaGetSymbolAddress((void**)&xC,  g_xC);
    cudaGetSymbolAddress((void**)&G,   g_G);

    const int SMEM_PG = 4 * 128 * 37 * 4;         // 75776 B
    const int SMEM_CO = (64 * 216 + 1728) * 4;    // 62208 B
    cudaFuncSetAttribute(pac_gemm_kernel, cudaFuncAttributeMaxDynamicSharedMemorySize, SMEM_PG);
    cudaFuncSetAttribute(conv_out_kernel, cudaFuncAttributeMaxDynamicSharedMemorySize, SMEM_CO);

    // stage 1: collapsed double inorm-residual (256, 64, 64)
    dinorm_kernel<<<256, 512>>>(x, xA, 64 * 64);

    // g2 = conv3x3(ef_lv2; 128->256 @128x128)
    conv_mma_kernel<<<dim3(1, 128, 2), 256>>>(ef_lv2, w_adj2, b_adj2, g2, 128, 128, 128);

    // kk1 from g2
    kk_kernel<<<dim3(4, 32), 128>>>(g2, kk1, 256, 128, 128);

    // pac1: GEMM (M=4096, N=1152, K=256) + apply -> xB (128,128,128)
    pac_gemm_kernel<<<dim3(32, 9), 256, SMEM_PG>>>(xA, w_pac16, G, 256, 1152, 4096);
    pac_apply_kernel<<<dim3(2, 16, 128), 128>>>(G, kk1, b_pac16, xB, 64, 64);

    dinorm_kernel<<<128, 512>>>(xB, xB, 128 * 128);

    // g1 = conv3x3(ef_lv1; 64->128 @256x256)
    conv_mma_kernel<<<dim3(2, 256, 1), 256>>>(ef_lv1, w_adj1, b_adj1, g1, 64, 256, 256);

    // kk2 from g1
    kk_kernel<<<dim3(8, 64), 128>>>(g1, kk2, 128, 256, 256);

    // pac2: GEMM (M=16384, N=576, K=128) + apply -> xC (64,256,256)
    pac_gemm_kernel<<<dim3(128, 5), 256, SMEM_PG>>>(xB, w_pac20, G, 128, 576, 16384);
    pac_apply_kernel<<<dim3(4, 32, 64), 128>>>(G, kk2, b_pac20, xC, 128, 128);

    dinorm_kernel<<<64, 512>>>(xC, xC, 256 * 256);

    // final conv: 64->3 @256x256 (single-barrier, fp32)
    conv_out_kernel<<<dim3(8, 64), dim3(8, 4, 3), SMEM_CO>>>(xC, w_out, b_out, outp, 256, 256);
}